// round 2
// baseline (speedup 1.0000x reference)
#include <cuda_runtime.h>

#define NN  50000
#define RR  50
#define BB  30
#define EE  1000000
// F_IN = H = 64, C = 8

// ---------------- device scratch (no allocations allowed) ----------------
__device__ int   g_cnt[NN * RR];      // edge count per (dst, rel)
__device__ int   g_relcnt[RR];
__device__ int   g_reloff[RR + 1];
__device__ int   g_cursor[RR];
__device__ float g_sedge[EE];         // per-edge 1/cnt scale
__device__ int   g_perm[EE];          // edges sorted (bucketed) by relation
__device__ float g_W[RR * 64 * 64];   // per-relation folded weights
__device__ float g_h[NN * 64];        // hidden (post-ReLU)
__device__ float g_acc[NN * 64];      // layer output accumulator

// ---------------- setup kernels ----------------
__global__ void k_zero() {
    for (int i = blockIdx.x * blockDim.x + threadIdx.x; i < NN * RR;
         i += gridDim.x * blockDim.x)
        g_cnt[i] = 0;
    if (blockIdx.x == 0 && threadIdx.x < RR) g_relcnt[threadIdx.x] = 0;
}

__global__ void k_hist(const int* __restrict__ ei, const int* __restrict__ et) {
    __shared__ int sh[RR];
    if (threadIdx.x < RR) sh[threadIdx.x] = 0;
    __syncthreads();
    for (int e = blockIdx.x * blockDim.x + threadIdx.x; e < EE;
         e += gridDim.x * blockDim.x) {
        int d = ei[EE + e];
        int r = et[e];
        atomicAdd(&g_cnt[d * RR + r], 1);
        atomicAdd(&sh[r], 1);
    }
    __syncthreads();
    if (threadIdx.x < RR) atomicAdd(&g_relcnt[threadIdx.x], sh[threadIdx.x]);
}

__global__ void k_sedge(const int* __restrict__ ei, const int* __restrict__ et) {
    for (int e = blockIdx.x * blockDim.x + threadIdx.x; e < EE;
         e += gridDim.x * blockDim.x) {
        int d = ei[EE + e];
        int r = et[e];
        g_sedge[e] = 1.0f / (float)g_cnt[d * RR + r];
    }
}

__global__ void k_scan() {
    if (threadIdx.x == 0) {
        int acc = 0;
        for (int r = 0; r < RR; r++) {
            g_reloff[r] = acc;
            g_cursor[r] = acc;
            acc += g_relcnt[r];
        }
        g_reloff[RR] = acc;
    }
}

#define PCHUNK 4096
__global__ void k_perm(const int* __restrict__ et) {
    __shared__ int scnt[RR], sbase[RR], soff[RR];
    int lo = blockIdx.x * PCHUNK;
    int hi = min(lo + PCHUNK, EE);
    if (threadIdx.x < RR) { scnt[threadIdx.x] = 0; soff[threadIdx.x] = 0; }
    __syncthreads();
    for (int e = lo + threadIdx.x; e < hi; e += blockDim.x)
        atomicAdd(&scnt[et[e]], 1);
    __syncthreads();
    if (threadIdx.x < RR)
        sbase[threadIdx.x] = atomicAdd(&g_cursor[threadIdx.x], scnt[threadIdx.x]);
    __syncthreads();
    for (int e = lo + threadIdx.x; e < hi; e += blockDim.x) {
        int r = et[e];
        int p = sbase[r] + atomicAdd(&soff[r], 1);
        g_perm[p] = e;
    }
}

// ---------------- per-layer kernels ----------------
// W[r,i,o] = sum_b comp[r,b] * bases[b,i,o]
__global__ void k_W(const float* __restrict__ comp, const float* __restrict__ bases,
                    int dout) {
    int total = RR * 64 * dout;
    for (int idx = blockIdx.x * blockDim.x + threadIdx.x; idx < total;
         idx += gridDim.x * blockDim.x) {
        int r = idx / (64 * dout);
        int rem = idx % (64 * dout);
        int i = rem / dout;
        int o = rem % dout;
        float w = 0.0f;
        #pragma unroll 6
        for (int b = 0; b < BB; b++)
            w = fmaf(comp[r * BB + b], bases[(b * 64 + i) * dout + o], w);
        g_W[idx] = w;
    }
}

// out[n,o] = bias[o] + sum_i x[n,i] * root[i,o]   (initializes accumulator)
__global__ void k_root(const float* __restrict__ x, const float* __restrict__ root,
                       const float* __restrict__ bias, float* __restrict__ out,
                       int dout) {
    int idx = blockIdx.x * blockDim.x + threadIdx.x;
    if (idx >= NN * dout) return;
    int n = idx / dout;
    int o = idx % dout;
    float s = bias[o];
    const float4* xr = (const float4*)(x + n * 64);
    #pragma unroll
    for (int i = 0; i < 16; i++) {
        float4 v = xr[i];
        s = fmaf(v.x, root[(4 * i + 0) * dout + o], s);
        s = fmaf(v.y, root[(4 * i + 1) * dout + o], s);
        s = fmaf(v.z, root[(4 * i + 2) * dout + o], s);
        s = fmaf(v.w, root[(4 * i + 3) * dout + o], s);
    }
    out[idx] = s;
}

// Edge transform + scatter. Blocks bucketed per relation (blockIdx.y).
// Each thread owns one W column (registers); x broadcast via shared.
template <int DOUT>
__global__ __launch_bounds__(256) void k_edge(const float* __restrict__ xin,
                                              const int* __restrict__ ei,
                                              float* __restrict__ out) {
    constexpr int SLOTS = 256 / DOUT;
    int r = blockIdx.y;
    int lo = g_reloff[r];
    int hi = g_reloff[r + 1];
    int slot = threadIdx.x / DOUT;
    int o = threadIdx.x % DOUT;

    const float* Wr = g_W + r * 64 * DOUT;
    float w[64];
    #pragma unroll
    for (int i = 0; i < 64; i++) w[i] = Wr[i * DOUT + o];

    __shared__ float xs[SLOTS][64];

    for (int base = lo + blockIdx.x * SLOTS; base < hi; base += gridDim.x * SLOTS) {
        int idx = base + slot;
        int src = 0, dst = 0;
        float s = 0.0f;
        bool act = (idx < hi);
        if (act) {
            int e = g_perm[idx];
            src = ei[e];
            dst = ei[EE + e];
            s = g_sedge[e];
        }
        __syncthreads();
        if (act) {
            #pragma unroll
            for (int i = o; i < 64; i += DOUT) xs[slot][i] = xin[src * 64 + i];
        }
        __syncthreads();
        if (act) {
            float acc = 0.0f;
            const float4* xv = (const float4*)xs[slot];
            #pragma unroll
            for (int i = 0; i < 16; i++) {
                float4 v = xv[i];
                acc = fmaf(v.x, w[4 * i + 0], acc);
                acc = fmaf(v.y, w[4 * i + 1], acc);
                acc = fmaf(v.z, w[4 * i + 2], acc);
                acc = fmaf(v.w, w[4 * i + 3], acc);
            }
            atomicAdd(&out[dst * DOUT + o], s * acc);
        }
    }
}

__global__ void k_relu(const float* __restrict__ in, float* __restrict__ outp) {
    for (int i = blockIdx.x * blockDim.x + threadIdx.x; i < NN * 64;
         i += gridDim.x * blockDim.x)
        outp[i] = fmaxf(in[i], 0.0f);
}

__global__ void k_lsm(const float* __restrict__ acc, float* __restrict__ outp) {
    int n = blockIdx.x * blockDim.x + threadIdx.x;
    if (n >= NN) return;
    float v[8];
    #pragma unroll
    for (int c = 0; c < 8; c++) v[c] = acc[n * 8 + c];
    float m = v[0];
    #pragma unroll
    for (int c = 1; c < 8; c++) m = fmaxf(m, v[c]);
    float ssum = 0.0f;
    #pragma unroll
    for (int c = 0; c < 8; c++) ssum += expf(v[c] - m);
    float l = m + logf(ssum);
    #pragma unroll
    for (int c = 0; c < 8; c++) outp[n * 8 + c] = v[c] - l;
}

// ---------------- launch ----------------
extern "C" void kernel_launch(void* const* d_in, const int* in_sizes, int n_in,
                              void* d_out, int out_size) {
    const float* x     = (const float*)d_in[0];
    const int*   ei    = (const int*)d_in[1];
    const int*   et    = (const int*)d_in[2];
    const float* bases0 = (const float*)d_in[3];
    const float* comp0  = (const float*)d_in[4];
    const float* root0  = (const float*)d_in[5];
    const float* bias0  = (const float*)d_in[6];
    const float* bases1 = (const float*)d_in[7];
    const float* comp1  = (const float*)d_in[8];
    const float* root1  = (const float*)d_in[9];
    const float* bias1  = (const float*)d_in[10];
    const float* bases2 = (const float*)d_in[11];
    const float* comp2  = (const float*)d_in[12];
    const float* root2  = (const float*)d_in[13];
    const float* bias2  = (const float*)d_in[14];
    float* out = (float*)d_out;

    float *pH = nullptr, *pAcc = nullptr;
    cudaGetSymbolAddress((void**)&pH, g_h);
    cudaGetSymbolAddress((void**)&pAcc, g_acc);

    // ---- shared setup (seg counts, per-edge scale, relation buckets) ----
    k_zero<<<2048, 256>>>();
    k_hist<<<2048, 256>>>(ei, et);
    k_sedge<<<2048, 256>>>(ei, et);
    k_scan<<<1, 32>>>();
    k_perm<<<(EE + PCHUNK - 1) / PCHUNK, 256>>>(et);

    // ---- layer 0: x(64) -> 64 ----
    k_W<<<(RR * 64 * 64 + 255) / 256, 256>>>(comp0, bases0, 64);
    k_root<<<(NN * 64 + 255) / 256, 256>>>(x, root0, bias0, pAcc, 64);
    k_edge<64><<<dim3(28, RR), 256>>>(x, ei, pAcc);
    k_relu<<<2048, 256>>>(pAcc, pH);

    // ---- layer 1: 64 -> 64 ----
    k_W<<<(RR * 64 * 64 + 255) / 256, 256>>>(comp1, bases1, 64);
    k_root<<<(NN * 64 + 255) / 256, 256>>>(pH, root1, bias1, pAcc, 64);
    k_edge<64><<<dim3(28, RR), 256>>>(pH, ei, pAcc);
    k_relu<<<2048, 256>>>(pAcc, pH);

    // ---- layer 2: 64 -> 8, then log_softmax ----
    k_W<<<(RR * 64 * 8 + 255) / 256, 256>>>(comp2, bases2, 8);
    k_root<<<(NN * 8 + 255) / 256, 256>>>(pH, root2, bias2, pAcc, 8);
    k_edge<8><<<dim3(16, RR), 256>>>(pH, ei, pAcc);
    k_lsm<<<(NN + 255) / 256, 256>>>(pAcc, out);
}

// round 3
// speedup vs baseline: 1.0115x; 1.0115x over previous
#include <cuda_runtime.h>

#define NN  50000
#define RR  50
#define BB  30
#define EE  1000000
// F_IN = H = 64, C = 8

// ---------------- device scratch (no allocations allowed) ----------------
__device__ int   g_cnt[NN * RR];      // edge count per (dst, rel)
__device__ int   g_relcnt[RR];
__device__ int   g_reloff[RR + 1];
__device__ int   g_cursor[RR];
__device__ float g_sedge[EE];         // per-edge 1/cnt scale
__device__ int   g_perm[EE];          // edges bucketed by relation
__device__ float g_W[RR * 64 * 64];   // per-relation folded weights
__device__ float g_h[NN * 64];        // hidden (post-ReLU)
__device__ float g_acc[NN * 64];      // layer output accumulator

// packed f32x2 FMA: d = a*b + d (componentwise on two packed fp32)
__device__ __forceinline__ void ffma2(unsigned long long& d,
                                      unsigned long long a,
                                      unsigned long long b) {
    asm("fma.rn.f32x2 %0, %1, %2, %0;" : "+l"(d) : "l"(a), "l"(b));
}
__device__ __forceinline__ float pairsum(unsigned long long d) {
    return __uint_as_float((unsigned)(d & 0xffffffffULL)) +
           __uint_as_float((unsigned)(d >> 32));
}
__device__ __forceinline__ unsigned long long packf2(float a, float b) {
    return (unsigned long long)__float_as_uint(a) |
           ((unsigned long long)__float_as_uint(b) << 32);
}

// ---------------- setup kernels ----------------
__global__ void k_zero() {
    for (int i = blockIdx.x * blockDim.x + threadIdx.x; i < NN * RR;
         i += gridDim.x * blockDim.x)
        g_cnt[i] = 0;
    if (blockIdx.x == 0 && threadIdx.x < RR) g_relcnt[threadIdx.x] = 0;
}

__global__ void k_hist(const int* __restrict__ ei, const int* __restrict__ et) {
    __shared__ int sh[RR];
    if (threadIdx.x < RR) sh[threadIdx.x] = 0;
    __syncthreads();
    for (int e = blockIdx.x * blockDim.x + threadIdx.x; e < EE;
         e += gridDim.x * blockDim.x) {
        int d = ei[EE + e];
        int r = et[e];
        atomicAdd(&g_cnt[d * RR + r], 1);
        atomicAdd(&sh[r], 1);
    }
    __syncthreads();
    if (threadIdx.x < RR) atomicAdd(&g_relcnt[threadIdx.x], sh[threadIdx.x]);
}

__global__ void k_sedge(const int* __restrict__ ei, const int* __restrict__ et) {
    for (int e = blockIdx.x * blockDim.x + threadIdx.x; e < EE;
         e += gridDim.x * blockDim.x) {
        int d = ei[EE + e];
        int r = et[e];
        g_sedge[e] = 1.0f / (float)g_cnt[d * RR + r];
    }
}

__global__ void k_scan() {
    if (threadIdx.x == 0) {
        int acc = 0;
        for (int r = 0; r < RR; r++) {
            g_reloff[r] = acc;
            g_cursor[r] = acc;
            acc += g_relcnt[r];
        }
        g_reloff[RR] = acc;
    }
}

#define PCHUNK 4096
__global__ void k_perm(const int* __restrict__ et) {
    __shared__ int scnt[RR], sbase[RR], soff[RR];
    int lo = blockIdx.x * PCHUNK;
    int hi = min(lo + PCHUNK, EE);
    if (threadIdx.x < RR) { scnt[threadIdx.x] = 0; soff[threadIdx.x] = 0; }
    __syncthreads();
    for (int e = lo + threadIdx.x; e < hi; e += blockDim.x)
        atomicAdd(&scnt[et[e]], 1);
    __syncthreads();
    if (threadIdx.x < RR)
        sbase[threadIdx.x] = atomicAdd(&g_cursor[threadIdx.x], scnt[threadIdx.x]);
    __syncthreads();
    for (int e = lo + threadIdx.x; e < hi; e += blockDim.x) {
        int r = et[e];
        int p = sbase[r] + atomicAdd(&soff[r], 1);
        g_perm[p] = e;
    }
}

// ---------------- per-layer kernels ----------------
__global__ void k_W(const float* __restrict__ comp, const float* __restrict__ bases,
                    int dout) {
    int total = RR * 64 * dout;
    for (int idx = blockIdx.x * blockDim.x + threadIdx.x; idx < total;
         idx += gridDim.x * blockDim.x) {
        int r = idx / (64 * dout);
        int rem = idx % (64 * dout);
        int i = rem / dout;
        int o = rem % dout;
        float w = 0.0f;
        #pragma unroll 6
        for (int b = 0; b < BB; b++)
            w = fmaf(comp[r * BB + b], bases[(b * 64 + i) * dout + o], w);
        g_W[idx] = w;
    }
}

__global__ void k_root(const float* __restrict__ x, const float* __restrict__ root,
                       const float* __restrict__ bias, float* __restrict__ out,
                       int dout) {
    int idx = blockIdx.x * blockDim.x + threadIdx.x;
    if (idx >= NN * dout) return;
    int n = idx / dout;
    int o = idx % dout;
    float s = bias[o];
    const float4* xr = (const float4*)(x + n * 64);
    #pragma unroll
    for (int i = 0; i < 16; i++) {
        float4 v = xr[i];
        s = fmaf(v.x, root[(4 * i + 0) * dout + o], s);
        s = fmaf(v.y, root[(4 * i + 1) * dout + o], s);
        s = fmaf(v.z, root[(4 * i + 2) * dout + o], s);
        s = fmaf(v.w, root[(4 * i + 3) * dout + o], s);
    }
    out[idx] = s;
}

// Edge transform + scatter: double-buffered pipeline, f32x2 FMA.
// Blocks bucketed per relation (blockIdx.y). Thread owns one W column.
template <int DOUT>
__global__ __launch_bounds__(256, 2) void k_edge(const float* __restrict__ xin,
                                                 const int* __restrict__ ei,
                                                 float* __restrict__ out) {
    constexpr int SLOTS = 256 / DOUT;
    int r = blockIdx.y;
    int lo = g_reloff[r];
    int hi = g_reloff[r + 1];
    int slot = threadIdx.x / DOUT;
    int o = threadIdx.x % DOUT;

    // W column packed into 32 f32x2 registers: w2[i] covers dims (2i, 2i+1)
    const float* Wr = g_W + r * 64 * DOUT;
    unsigned long long w2[32];
    #pragma unroll
    for (int i = 0; i < 32; i++)
        w2[i] = packf2(Wr[(2 * i) * DOUT + o], Wr[(2 * i + 1) * DOUT + o]);

    __shared__ float xs[2][SLOTS][64];

    int stride = gridDim.x * SLOTS;
    int base0 = lo + blockIdx.x * SLOTS;

    // prologue: load batch 0
    int idx = base0 + slot;
    int dst = 0;
    float s = 0.0f;
    bool act = (idx < hi);
    if (act) {
        int e = g_perm[idx];
        int src = ei[e];
        dst = ei[EE + e];
        s = g_sedge[e];
        #pragma unroll
        for (int i = o; i < 64; i += DOUT) xs[0][slot][i] = xin[src * 64 + i];
    }
    __syncthreads();

    int buf = 0;
    for (int base = base0; base < hi; base += stride) {
        // prefetch batch t+1 into the other buffer (no sync needed yet)
        int nidx = base + stride + slot;
        int ndst = 0;
        float ns = 0.0f;
        bool nact = (base + stride < hi) && (nidx < hi);
        if (nact) {
            int e = g_perm[nidx];
            int src = ei[e];
            ndst = ei[EE + e];
            ns = g_sedge[e];
            #pragma unroll
            for (int i = o; i < 64; i += DOUT)
                xs[buf ^ 1][slot][i] = xin[src * 64 + i];
        }
        // compute batch t
        if (act) {
            const ulonglong2* xv = (const ulonglong2*)xs[buf][slot];
            unsigned long long a0 = 0, a1 = 0;
            #pragma unroll
            for (int i = 0; i < 16; i++) {
                ulonglong2 v = xv[i];           // dims 4i..4i+3 as two f32x2
                ffma2(a0, v.x, w2[2 * i]);
                ffma2(a1, v.y, w2[2 * i + 1]);
            }
            float acc = pairsum(a0) + pairsum(a1);
            atomicAdd(&out[dst * DOUT + o], s * acc);
        }
        __syncthreads();
        act = nact;
        dst = ndst;
        s = ns;
        buf ^= 1;
    }
}

__global__ void k_relu(const float* __restrict__ in, float* __restrict__ outp) {
    for (int i = blockIdx.x * blockDim.x + threadIdx.x; i < NN * 64;
         i += gridDim.x * blockDim.x)
        outp[i] = fmaxf(in[i], 0.0f);
}

__global__ void k_lsm(const float* __restrict__ acc, float* __restrict__ outp) {
    int n = blockIdx.x * blockDim.x + threadIdx.x;
    if (n >= NN) return;
    float v[8];
    #pragma unroll
    for (int c = 0; c < 8; c++) v[c] = acc[n * 8 + c];
    float m = v[0];
    #pragma unroll
    for (int c = 1; c < 8; c++) m = fmaxf(m, v[c]);
    float ssum = 0.0f;
    #pragma unroll
    for (int c = 0; c < 8; c++) ssum += expf(v[c] - m);
    float l = m + logf(ssum);
    #pragma unroll
    for (int c = 0; c < 8; c++) outp[n * 8 + c] = v[c] - l;
}

// ---------------- launch ----------------
extern "C" void kernel_launch(void* const* d_in, const int* in_sizes, int n_in,
                              void* d_out, int out_size) {
    const float* x     = (const float*)d_in[0];
    const int*   ei    = (const int*)d_in[1];
    const int*   et    = (const int*)d_in[2];
    const float* bases0 = (const float*)d_in[3];
    const float* comp0  = (const float*)d_in[4];
    const float* root0  = (const float*)d_in[5];
    const float* bias0  = (const float*)d_in[6];
    const float* bases1 = (const float*)d_in[7];
    const float* comp1  = (const float*)d_in[8];
    const float* root1  = (const float*)d_in[9];
    const float* bias1  = (const float*)d_in[10];
    const float* bases2 = (const float*)d_in[11];
    const float* comp2  = (const float*)d_in[12];
    const float* root2  = (const float*)d_in[13];
    const float* bias2  = (const float*)d_in[14];
    float* out = (float*)d_out;

    float *pH = nullptr, *pAcc = nullptr;
    cudaGetSymbolAddress((void**)&pH, g_h);
    cudaGetSymbolAddress((void**)&pAcc, g_acc);

    // ---- shared setup (seg counts, per-edge scale, relation buckets) ----
    k_zero<<<2048, 256>>>();
    k_hist<<<2048, 256>>>(ei, et);
    k_sedge<<<2048, 256>>>(ei, et);
    k_scan<<<1, 32>>>();
    k_perm<<<(EE + PCHUNK - 1) / PCHUNK, 256>>>(et);

    // ---- layer 0: x(64) -> 64 ----
    k_W<<<(RR * 64 * 64 + 255) / 256, 256>>>(comp0, bases0, 64);
    k_root<<<(NN * 64 + 255) / 256, 256>>>(x, root0, bias0, pAcc, 64);
    k_edge<64><<<dim3(28, RR), 256>>>(x, ei, pAcc);
    k_relu<<<2048, 256>>>(pAcc, pH);

    // ---- layer 1: 64 -> 64 ----
    k_W<<<(RR * 64 * 64 + 255) / 256, 256>>>(comp1, bases1, 64);
    k_root<<<(NN * 64 + 255) / 256, 256>>>(pH, root1, bias1, pAcc, 64);
    k_edge<64><<<dim3(28, RR), 256>>>(pH, ei, pAcc);
    k_relu<<<2048, 256>>>(pAcc, pH);

    // ---- layer 2: 64 -> 8, then log_softmax ----
    k_W<<<(RR * 64 * 8 + 255) / 256, 256>>>(comp2, bases2, 8);
    k_root<<<(NN * 8 + 255) / 256, 256>>>(pH, root2, bias2, pAcc, 8);
    k_edge<8><<<dim3(16, RR), 256>>>(pH, ei, pAcc);
    k_lsm<<<(NN + 255) / 256, 256>>>(pAcc, out);
}

// round 5
// speedup vs baseline: 1.5797x; 1.5618x over previous
#include <cuda_runtime.h>

#define NN  50000
#define RR  50
#define BB  30
#define EE  1000000
// F_IN = H = 64, C = 8

// ---------------- device scratch ----------------
__device__ int   g_cnt[NN * RR];
__device__ int   g_relcnt[RR];
__device__ int   g_reloff[RR + 1];
__device__ int   g_cursor[RR];
__device__ int   g_perm[EE];
__device__ int   g_esrc[EE];        // meta in bucket order
__device__ int   g_edst[EE];
__device__ float g_es[EE];
__device__ float g_W[RR * 64 * 64];
__device__ float g_h[NN * 64];
__device__ float g_msg[NN * 64];    // stays zeroed between uses (restored by k_combine)
__device__ float g_acc[NN * 64];

// ---------------- helpers ----------------
__device__ __forceinline__ void ffma2(unsigned long long& d,
                                      unsigned long long a,
                                      unsigned long long b) {
    asm("fma.rn.f32x2 %0, %1, %2, %0;" : "+l"(d) : "l"(a), "l"(b));
}
__device__ __forceinline__ float pairsum(unsigned long long d) {
    return __uint_as_float((unsigned)(d & 0xffffffffULL)) +
           __uint_as_float((unsigned)(d >> 32));
}
__device__ __forceinline__ unsigned long long packf2(float a, float b) {
    return (unsigned long long)__float_as_uint(a) |
           ((unsigned long long)__float_as_uint(b) << 32);
}
__device__ __forceinline__ void cp16(void* s, const void* g) {
    unsigned sa = (unsigned)__cvta_generic_to_shared(s);
    asm volatile("cp.async.cg.shared.global [%0], [%1], 16;\n" :: "r"(sa), "l"(g));
}
__device__ __forceinline__ void cp_commit() { asm volatile("cp.async.commit_group;\n"); }
template <int N>
__device__ __forceinline__ void cp_wait() {
    asm volatile("cp.async.wait_group %0;\n" :: "n"(N));
}
__device__ __forceinline__ void barsync64(int id) {
    asm volatile("bar.sync %0, 64;\n" :: "r"(id) : "memory");
}

// ---------------- setup kernels ----------------
__global__ void k_zero() {
    for (int i = blockIdx.x * blockDim.x + threadIdx.x; i < NN * RR;
         i += gridDim.x * blockDim.x)
        g_cnt[i] = 0;
    if (blockIdx.x == 0 && threadIdx.x < RR) g_relcnt[threadIdx.x] = 0;
}

__global__ void k_hist(const int* __restrict__ ei, const int* __restrict__ et) {
    __shared__ int sh[RR];
    if (threadIdx.x < RR) sh[threadIdx.x] = 0;
    __syncthreads();
    for (int e = blockIdx.x * blockDim.x + threadIdx.x; e < EE;
         e += gridDim.x * blockDim.x) {
        int d = ei[EE + e];
        int r = et[e];
        atomicAdd(&g_cnt[d * RR + r], 1);
        atomicAdd(&sh[r], 1);
    }
    __syncthreads();
    if (threadIdx.x < RR) atomicAdd(&g_relcnt[threadIdx.x], sh[threadIdx.x]);
}

__global__ void k_scan() {
    if (threadIdx.x == 0) {
        int acc = 0;
        for (int r = 0; r < RR; r++) {
            g_reloff[r] = acc;
            g_cursor[r] = acc;
            acc += g_relcnt[r];
        }
        g_reloff[RR] = acc;
    }
}

#define PCHUNK 4096
__global__ void k_perm(const int* __restrict__ et) {
    __shared__ int scnt[RR], sbase[RR], soff[RR];
    int lo = blockIdx.x * PCHUNK;
    int hi = min(lo + PCHUNK, EE);
    if (threadIdx.x < RR) { scnt[threadIdx.x] = 0; soff[threadIdx.x] = 0; }
    __syncthreads();
    for (int e = lo + threadIdx.x; e < hi; e += blockDim.x)
        atomicAdd(&scnt[et[e]], 1);
    __syncthreads();
    if (threadIdx.x < RR)
        sbase[threadIdx.x] = atomicAdd(&g_cursor[threadIdx.x], scnt[threadIdx.x]);
    __syncthreads();
    for (int e = lo + threadIdx.x; e < hi; e += blockDim.x) {
        int r = et[e];
        int p = sbase[r] + atomicAdd(&soff[r], 1);
        g_perm[p] = e;
    }
}

// meta gather (y==0) fused with layer-0 W fold (y==1)
__global__ void k_metaW0(const int* __restrict__ ei, const int* __restrict__ et,
                         const float* __restrict__ comp, const float* __restrict__ bases) {
    if (blockIdx.y == 0) {
        for (int p = blockIdx.x * blockDim.x + threadIdx.x; p < EE;
             p += gridDim.x * blockDim.x) {
            int e = g_perm[p];
            int s = ei[e], d = ei[EE + e], rr = et[e];
            g_esrc[p] = s;
            g_edst[p] = d;
            g_es[p] = 1.0f / (float)g_cnt[d * RR + rr];
        }
    } else {
        for (int idx = blockIdx.x * blockDim.x + threadIdx.x; idx < RR * 64 * 64;
             idx += gridDim.x * blockDim.x) {
            int r = idx >> 12, rem = idx & 4095, i = rem >> 6, oo = rem & 63;
            float wv = 0.0f;
            #pragma unroll 6
            for (int b = 0; b < BB; b++)
                wv = fmaf(comp[r * BB + b], bases[(b * 64 + i) * 64 + oo], wv);
            g_W[idx] = wv;
        }
    }
}

__global__ void k_W(const float* __restrict__ comp, const float* __restrict__ bases,
                    int dout) {
    int total = RR * 64 * dout;
    for (int idx = blockIdx.x * blockDim.x + threadIdx.x; idx < total;
         idx += gridDim.x * blockDim.x) {
        int r = idx / (64 * dout);
        int rem = idx % (64 * dout);
        int i = rem / dout;
        int o = rem % dout;
        float w = 0.0f;
        #pragma unroll 6
        for (int b = 0; b < BB; b++)
            w = fmaf(comp[r * BB + b], bases[(b * 64 + i) * dout + o], w);
        g_W[idx] = w;
    }
}

// ---------------- edge kernels ----------------
// 64-out edge transform: 64-thread groups, cp.async depth-3 pipeline,
// one named barrier per edge, f32x2 FMA, RED scatter.
__global__ __launch_bounds__(256, 2) void k_edge64(const float* __restrict__ xin,
                                                   float* __restrict__ msg, int gx4) {
    constexpr int DEPTH = 4;
    int r = blockIdx.y;
    int lo = g_reloff[r], hi = g_reloff[r + 1];
    int cnt = hi - lo;
    int group = threadIdx.x >> 6;
    int o = threadIdx.x & 63;
    int gid = (blockIdx.x << 2) + group;
    int chunk = (cnt + gx4 - 1) / gx4;
    int gbeg = lo + gid * chunk;
    int n = min(chunk, hi - gbeg);          // group-uniform; may be <= 0

    const float* Wr = g_W + (r << 12);
    unsigned long long w2[32];
    #pragma unroll
    for (int i = 0; i < 32; i++)
        w2[i] = packf2(Wr[(2 * i) * 64 + o], Wr[(2 * i + 1) * 64 + o]);

    __shared__ __align__(16) float xs[4][DEPTH][64];
    __shared__ int   sdst[4][DEPTH];
    __shared__ float ssc[4][DEPTH];

    auto issue = [&](int k) {
        if (k < n) {
            int slot = k & (DEPTH - 1);
            int idx = gbeg + k;
            if (o < 16) {
                int src = __ldg(&g_esrc[idx]);
                cp16(&xs[group][slot][o << 2], xin + ((size_t)src << 6) + (o << 2));
            } else if (o == 16) {
                sdst[group][slot] = __ldg(&g_edst[idx]);
            } else if (o == 17) {
                ssc[group][slot] = __ldg(&g_es[idx]);
            }
        }
        if (o < 16) cp_commit();
    };

    issue(0); issue(1); issue(2);
    for (int k = 0; k < n; k++) {
        int slot = k & (DEPTH - 1);
        if (o < 16) cp_wait<2>();
        barsync64(group + 1);               // data for k ready; k-1 fully consumed
        int dst = sdst[group][slot];
        float s = ssc[group][slot];
        const ulonglong2* xv = (const ulonglong2*)xs[group][slot];
        unsigned long long a0 = 0, a1 = 0;
        #pragma unroll
        for (int i = 0; i < 16; i++) {
            ulonglong2 v = xv[i];
            ffma2(a0, v.x, w2[2 * i]);
            ffma2(a1, v.y, w2[2 * i + 1]);
        }
        atomicAdd(&msg[(dst << 6) + o], s * (pairsum(a0) + pairsum(a1)));
        issue(k + 3);                       // overwrites slot (k-1)&3: safe past barrier
    }
}

// 8-out edge transform: warp-private pipeline, 4 edges per warp iteration.
__global__ __launch_bounds__(256, 2) void k_edge8(const float* __restrict__ xin,
                                                  float* __restrict__ msg, int nw) {
    constexpr int DEPTH = 4;
    int r = blockIdx.y;
    int lo = g_reloff[r], hi = g_reloff[r + 1];
    int cnt = hi - lo;
    int w = threadIdx.x >> 5;
    int lane = threadIdx.x & 31;
    int q = lane >> 3, o = lane & 7;
    int wid = (blockIdx.x << 3) + w;
    int chunk = (cnt + nw - 1) / nw;
    int wbeg = lo + wid * chunk;
    int n = min(chunk, hi - wbeg);
    int iters = (n + 3) >> 2;               // warp-uniform; n may be <= 0 -> iters <= 0

    const float* Wr = g_W + r * 512;
    unsigned long long w2[32];
    #pragma unroll
    for (int i = 0; i < 32; i++)
        w2[i] = packf2(Wr[(2 * i) * 8 + o], Wr[(2 * i + 1) * 8 + o]);

    __shared__ __align__(16) float xs[8][DEPTH][4][68];   // 68: bank-conflict pad
    __shared__ int   sdst[8][DEPTH][4];
    __shared__ float ssc[8][DEPTH][4];

    auto issue = [&](int it) {
        if (it < iters) {
            int slot = it & 3;
            int base = wbeg + (it << 2);
            #pragma unroll
            for (int c = lane; c < 64; c += 32) {
                int eq = c >> 4, p = c & 15;
                int idx = base + eq;
                if (idx < wbeg + n) {
                    int src = __ldg(&g_esrc[idx]);
                    cp16(&xs[w][slot][eq][p << 2], xin + ((size_t)src << 6) + (p << 2));
                }
            }
            if (lane < 4) {
                int idx = base + lane;
                if (idx < wbeg + n) {
                    sdst[w][slot][lane] = __ldg(&g_edst[idx]);
                    ssc[w][slot][lane]  = __ldg(&g_es[idx]);
                }
            }
        }
        cp_commit();
    };

    issue(0); issue(1); issue(2);
    for (int it = 0; it < iters; it++) {
        int slot = it & 3;
        cp_wait<2>();
        __syncwarp();
        int idx = wbeg + (it << 2) + q;
        if (idx < wbeg + n) {
            int dst = sdst[w][slot][q];
            float s = ssc[w][slot][q];
            const ulonglong2* xv = (const ulonglong2*)xs[w][slot][q];
            unsigned long long a0 = 0, a1 = 0;
            #pragma unroll
            for (int i = 0; i < 16; i++) {
                ulonglong2 v = xv[i];
                ffma2(a0, v.x, w2[2 * i]);
                ffma2(a1, v.y, w2[2 * i + 1]);
            }
            atomicAdd(&msg[(dst << 3) + o], s * (pairsum(a0) + pairsum(a1)));
        }
        issue(it + 3);
    }
}

// ---------------- epilogue kernels ----------------
// out = [relu]( msg + bias + x @ root ), and restore msg to zero.
__global__ void k_combine(const float* __restrict__ xin, const float* __restrict__ root,
                          const float* __restrict__ bias, float* __restrict__ msgio,
                          float* __restrict__ outp, int dout, int relu) {
    int idx = blockIdx.x * blockDim.x + threadIdx.x;
    if (idx >= NN * dout) return;
    int nd = idx / dout, o = idx - nd * dout;
    float s = bias[o] + msgio[idx];
    msgio[idx] = 0.0f;
    const float4* xr = (const float4*)(xin + (nd << 6));
    #pragma unroll
    for (int i = 0; i < 16; i++) {
        float4 v = xr[i];
        s = fmaf(v.x, root[(4 * i + 0) * dout + o], s);
        s = fmaf(v.y, root[(4 * i + 1) * dout + o], s);
        s = fmaf(v.z, root[(4 * i + 2) * dout + o], s);
        s = fmaf(v.w, root[(4 * i + 3) * dout + o], s);
    }
    outp[idx] = relu ? fmaxf(s, 0.0f) : s;
}

__global__ void k_lsm(const float* __restrict__ acc, float* __restrict__ outp) {
    int n = blockIdx.x * blockDim.x + threadIdx.x;
    if (n >= NN) return;
    float v[8];
    #pragma unroll
    for (int c = 0; c < 8; c++) v[c] = acc[n * 8 + c];
    float m = v[0];
    #pragma unroll
    for (int c = 1; c < 8; c++) m = fmaxf(m, v[c]);
    float ssum = 0.0f;
    #pragma unroll
    for (int c = 0; c < 8; c++) ssum += expf(v[c] - m);
    float l = m + logf(ssum);
    #pragma unroll
    for (int c = 0; c < 8; c++) outp[n * 8 + c] = v[c] - l;
}

// ---------------- launch ----------------
extern "C" void kernel_launch(void* const* d_in, const int* in_sizes, int n_in,
                              void* d_out, int out_size) {
    const float* x      = (const float*)d_in[0];
    const int*   ei     = (const int*)d_in[1];
    const int*   et     = (const int*)d_in[2];
    const float* bases0 = (const float*)d_in[3];
    const float* comp0  = (const float*)d_in[4];
    const float* root0  = (const float*)d_in[5];
    const float* bias0  = (const float*)d_in[6];
    const float* bases1 = (const float*)d_in[7];
    const float* comp1  = (const float*)d_in[8];
    const float* root1  = (const float*)d_in[9];
    const float* bias1  = (const float*)d_in[10];
    const float* bases2 = (const float*)d_in[11];
    const float* comp2  = (const float*)d_in[12];
    const float* root2  = (const float*)d_in[13];
    const float* bias2  = (const float*)d_in[14];
    float* out = (float*)d_out;

    float *pH = nullptr, *pMsg = nullptr, *pAcc = nullptr;
    cudaGetSymbolAddress((void**)&pH, g_h);
    cudaGetSymbolAddress((void**)&pMsg, g_msg);
    cudaGetSymbolAddress((void**)&pAcc, g_acc);

    const int GX = 24;   // edge64: groups per relation = GX*4
    const int GX8 = 8;   // edge8: warps per relation = GX8*8

    // setup (5 launches so k_edge64 L0 is launch index 5 for ncu -s 5)
    k_zero<<<2048, 256>>>();
    k_hist<<<2048, 256>>>(ei, et);
    k_scan<<<1, 32>>>();
    k_perm<<<(EE + PCHUNK - 1) / PCHUNK, 256>>>(et);
    k_metaW0<<<dim3(512, 2), 256>>>(ei, et, comp0, bases0);

    // layer 0
    k_edge64<<<dim3(GX, RR), 256>>>(x, pMsg, GX * 4);
    k_combine<<<(NN * 64 + 255) / 256, 256>>>(x, root0, bias0, pMsg, pH, 64, 1);

    // layer 1
    k_W<<<(RR * 64 * 64 + 255) / 256, 256>>>(comp1, bases1, 64);
    k_edge64<<<dim3(GX, RR), 256>>>(pH, pMsg, GX * 4);
    k_combine<<<(NN * 64 + 255) / 256, 256>>>(pH, root1, bias1, pMsg, pAcc, 64, 1);
    // pAcc holds relu'd hidden for layer 2 input (reuse as h2)

    // layer 2 (64 -> 8) + log_softmax
    k_W<<<(RR * 64 * 8 + 255) / 256, 256>>>(comp2, bases2, 8);
    k_edge8<<<dim3(GX8, RR), 256>>>(pAcc, pMsg, GX8 * 8);
    k_combine<<<(NN * 8 + 255) / 256, 256>>>(pAcc, root2, bias2, pMsg, pH, 8, 0);
    k_lsm<<<(NN + 255) / 256, 256>>>(pH, out);
}

// round 10
// speedup vs baseline: 2.2334x; 1.4138x over previous
#include <cuda_runtime.h>

#define NN  50000
#define RR  50
#define BB  30
#define EE  1000000
// F_IN = H = 64, C = 8

// ---------------- device scratch ----------------
__device__ int   g_cnt[NN * RR];
__device__ int   g_relcnt[RR];
__device__ int   g_reloff[RR + 1];
__device__ int   g_cursor[RR];
__device__ int   g_done;
__device__ int   g_esrc[EE];        // meta in bucket order
__device__ int   g_edst[EE];
__device__ float g_es[EE];
__device__ float g_W0[RR * 64 * 64];
__device__ float g_W1[RR * 64 * 64];
__device__ float g_W2[RR * 64 * 8];
__device__ float g_h[NN * 64];
__device__ float g_msg[NN * 64];    // zero between uses (restored by k_combine)
__device__ float g_acc[NN * 64];

// ---------------- helpers ----------------
__device__ __forceinline__ void ffma2(unsigned long long& d,
                                      unsigned long long a,
                                      unsigned long long b) {
    asm("fma.rn.f32x2 %0, %1, %2, %0;" : "+l"(d) : "l"(a), "l"(b));
}
__device__ __forceinline__ float pairsum(unsigned long long d) {
    return __uint_as_float((unsigned)(d & 0xffffffffULL)) +
           __uint_as_float((unsigned)(d >> 32));
}
__device__ __forceinline__ unsigned long long packf2(float a, float b) {
    return (unsigned long long)__float_as_uint(a) |
           ((unsigned long long)__float_as_uint(b) << 32);
}
__device__ __forceinline__ void cp16(void* s, const void* g) {
    unsigned sa = (unsigned)__cvta_generic_to_shared(s);
    asm volatile("cp.async.cg.shared.global [%0], [%1], 16;\n" :: "r"(sa), "l"(g));
}
__device__ __forceinline__ void cp_commit() { asm volatile("cp.async.commit_group;\n"); }
template <int N>
__device__ __forceinline__ void cp_wait() {
    asm volatile("cp.async.wait_group %0;\n" :: "n"(N));
}
__device__ __forceinline__ void barsync64(int id) {
    asm volatile("bar.sync %0, 64;\n" :: "r"(id) : "memory");
}

// ---------------- setup ----------------
__global__ void k_zero() {
    for (int i = blockIdx.x * blockDim.x + threadIdx.x; i < NN * RR;
         i += gridDim.x * blockDim.x)
        g_cnt[i] = 0;
    if (blockIdx.x == 0 && threadIdx.x < RR) g_relcnt[threadIdx.x] = 0;
}

// y==0: histogram (+ last block computes prefix scan)
// y==1/2/3: fold W for layers 0/1/2 (independent of hist)
__global__ void k_histW(const int* __restrict__ ei, const int* __restrict__ et,
                        const float* __restrict__ comp0, const float* __restrict__ bases0,
                        const float* __restrict__ comp1, const float* __restrict__ bases1,
                        const float* __restrict__ comp2, const float* __restrict__ bases2) {
    if (blockIdx.y == 0) {
        __shared__ int sh[RR];
        if (threadIdx.x < RR) sh[threadIdx.x] = 0;
        __syncthreads();
        for (int e = blockIdx.x * blockDim.x + threadIdx.x; e < EE;
             e += gridDim.x * blockDim.x) {
            int d = ei[EE + e];
            int r = et[e];
            atomicAdd(&g_cnt[d * RR + r], 1);
            atomicAdd(&sh[r], 1);
        }
        __syncthreads();
        if (threadIdx.x < RR) atomicAdd(&g_relcnt[threadIdx.x], sh[threadIdx.x]);
        __threadfence();
        if (threadIdx.x == 0) {
            int t = atomicAdd(&g_done, 1);
            if (t == gridDim.x - 1) {       // last hist block: do the scan
                int acc = 0;
                for (int r = 0; r < RR; r++) {
                    g_reloff[r] = acc;
                    g_cursor[r] = acc;
                    acc += g_relcnt[r];
                }
                g_reloff[RR] = acc;
                g_done = 0;                 // reset for next graph replay
                __threadfence();
            }
        }
    } else {
        const float* comp  = blockIdx.y == 1 ? comp0  : (blockIdx.y == 2 ? comp1  : comp2);
        const float* bases = blockIdx.y == 1 ? bases0 : (blockIdx.y == 2 ? bases1 : bases2);
        float* W  = blockIdx.y == 1 ? g_W0 : (blockIdx.y == 2 ? g_W1 : g_W2);
        int dout  = blockIdx.y == 3 ? 8 : 64;
        int total = RR * 64 * dout;
        for (int idx = blockIdx.x * blockDim.x + threadIdx.x; idx < total;
             idx += gridDim.x * blockDim.x) {
            int r = idx / (64 * dout);
            int rem = idx % (64 * dout);
            int i = rem / dout;
            int o = rem % dout;
            float w = 0.0f;
            #pragma unroll 6
            for (int b = 0; b < BB; b++)
                w = fmaf(comp[r * BB + b], bases[(b * 64 + i) * dout + o], w);
            W[idx] = w;
        }
    }
}

// bucket edges by relation, writing flat meta (src/dst/scale) directly
#define PCHUNK 4096
__global__ void k_permmeta(const int* __restrict__ ei, const int* __restrict__ et) {
    __shared__ int scnt[RR], sbase[RR], soff[RR];
    int lo = blockIdx.x * PCHUNK;
    int hi = min(lo + PCHUNK, EE);
    if (threadIdx.x < RR) { scnt[threadIdx.x] = 0; soff[threadIdx.x] = 0; }
    __syncthreads();
    for (int e = lo + threadIdx.x; e < hi; e += blockDim.x)
        atomicAdd(&scnt[et[e]], 1);
    __syncthreads();
    if (threadIdx.x < RR)
        sbase[threadIdx.x] = atomicAdd(&g_cursor[threadIdx.x], scnt[threadIdx.x]);
    __syncthreads();
    for (int e = lo + threadIdx.x; e < hi; e += blockDim.x) {
        int r = et[e];
        int p = sbase[r] + atomicAdd(&soff[r], 1);
        int s = ei[e], d = ei[EE + e];
        g_esrc[p] = s;
        g_edst[p] = d;
        g_es[p] = 1.0f / (float)g_cnt[d * RR + r];
    }
}

// ---------------- edge kernels ----------------
// 64-out edge transform: 64-thread groups, 8-edge batches, DEPTH-3 cp.async
// pipeline, ONE named barrier per 8 edges, f32x2 FMA, RED scatter.
__global__ __launch_bounds__(256, 2) void k_edge64(const float* __restrict__ xin,
                                                   const float* __restrict__ Wall,
                                                   float* __restrict__ msg, int ngroups) {
    constexpr int BATCH = 8;
    constexpr int DEPTH = 3;
    int r = blockIdx.y;
    int lo = g_reloff[r], hi = g_reloff[r + 1];
    int cnt = hi - lo;
    int group = threadIdx.x >> 6;
    int o = threadIdx.x & 63;
    int gid = (blockIdx.x << 2) + group;
    int chunk = (cnt + ngroups - 1) / ngroups;
    int gbeg = lo + gid * chunk;
    int n = min(chunk, hi - gbeg);          // group-uniform; may be <= 0
    int nb = (n + BATCH - 1) / BATCH;       // batches (may be <= 0)

    const float* Wr = Wall + (r << 12);
    unsigned long long w2[32];
    #pragma unroll
    for (int i = 0; i < 32; i++)
        w2[i] = packf2(Wr[(2 * i) * 64 + o], Wr[(2 * i + 1) * 64 + o]);

    __shared__ __align__(16) float xs[4][DEPTH][BATCH][64];
    __shared__ int   sdst[4][DEPTH][BATCH];
    __shared__ float ssc[4][DEPTH][BATCH];

    int j8 = o >> 3;            // edge within batch this thread gathers (0..7)
    int h8 = o & 7;             // 32B chunk within the row

    auto issue = [&](int t) {
        if (t < nb) {
            int slot = t % DEPTH;
            int base = gbeg + t * BATCH;
            int idx = base + j8;
            if (idx < gbeg + n) {
                int src = __ldg(&g_esrc[idx]);
                const float* xp = xin + ((size_t)src << 6) + (h8 << 3);
                float* sp = &xs[group][slot][j8][h8 << 3];
                cp16(sp, xp);
                cp16(sp + 4, xp + 4);
            }
            if (o >= 48) {
                int j = o & 7;
                int mi = base + j;
                if (mi < gbeg + n) {
                    if (o < 56) sdst[group][slot][j] = __ldg(&g_edst[mi]);
                    else        ssc[group][slot][j]  = __ldg(&g_es[mi]);
                }
            }
        }
        cp_commit();
    };

    issue(0); issue(1);
    for (int t = 0; t < nb; t++) {
        int slot = t % DEPTH;
        cp_wait<1>();
        barsync64(group + 1);               // batch t visible; batch t-1 consumed
        int nj = min(BATCH, n - t * BATCH);
        #pragma unroll
        for (int j = 0; j < BATCH; j++) {
            if (j < nj) {
                int dst = sdst[group][slot][j];
                float s = ssc[group][slot][j];
                const ulonglong2* xv = (const ulonglong2*)xs[group][slot][j];
                unsigned long long a0 = 0, a1 = 0;
                #pragma unroll
                for (int i = 0; i < 16; i++) {
                    ulonglong2 v = xv[i];
                    ffma2(a0, v.x, w2[2 * i]);
                    ffma2(a1, v.y, w2[2 * i + 1]);
                }
                atomicAdd(&msg[(dst << 6) + o], s * (pairsum(a0) + pairsum(a1)));
            }
        }
        issue(t + 2);                       // slot (t+2)%3 free: consumed before this bar
    }
}

// 8-out edge transform: warp-private pipeline, 4 edges per warp iteration.
__global__ __launch_bounds__(256, 2) void k_edge8(const float* __restrict__ xin,
                                                  float* __restrict__ msg, int nw) {
    constexpr int DEPTH = 4;
    int r = blockIdx.y;
    int lo = g_reloff[r], hi = g_reloff[r + 1];
    int cnt = hi - lo;
    int w = threadIdx.x >> 5;
    int lane = threadIdx.x & 31;
    int q = lane >> 3, o = lane & 7;
    int wid = (blockIdx.x << 3) + w;
    int chunk = (cnt + nw - 1) / nw;
    int wbeg = lo + wid * chunk;
    int n = min(chunk, hi - wbeg);
    int iters = (n + 3) >> 2;

    const float* Wr = g_W2 + r * 512;
    unsigned long long w2[32];
    #pragma unroll
    for (int i = 0; i < 32; i++)
        w2[i] = packf2(Wr[(2 * i) * 8 + o], Wr[(2 * i + 1) * 8 + o]);

    __shared__ __align__(16) float xs[8][DEPTH][4][68];
    __shared__ int   sdst[8][DEPTH][4];
    __shared__ float ssc[8][DEPTH][4];

    auto issue = [&](int it) {
        if (it < iters) {
            int slot = it & 3;
            int base = wbeg + (it << 2);
            #pragma unroll
            for (int c = lane; c < 64; c += 32) {
                int eq = c >> 4, p = c & 15;
                int idx = base + eq;
                if (idx < wbeg + n) {
                    int src = __ldg(&g_esrc[idx]);
                    cp16(&xs[w][slot][eq][p << 2], xin + ((size_t)src << 6) + (p << 2));
                }
            }
            if (lane < 4) {
                int idx = base + lane;
                if (idx < wbeg + n) {
                    sdst[w][slot][lane] = __ldg(&g_edst[idx]);
                    ssc[w][slot][lane]  = __ldg(&g_es[idx]);
                }
            }
        }
        cp_commit();
    };

    issue(0); issue(1); issue(2);
    for (int it = 0; it < iters; it++) {
        int slot = it & 3;
        cp_wait<2>();
        __syncwarp();
        int idx = wbeg + (it << 2) + q;
        if (idx < wbeg + n) {
            int dst = sdst[w][slot][q];
            float s = ssc[w][slot][q];
            const ulonglong2* xv = (const ulonglong2*)xs[w][slot][q];
            unsigned long long a0 = 0, a1 = 0;
            #pragma unroll
            for (int i = 0; i < 16; i++) {
                ulonglong2 v = xv[i];
                ffma2(a0, v.x, w2[2 * i]);
                ffma2(a1, v.y, w2[2 * i + 1]);
            }
            atomicAdd(&msg[(dst << 3) + o], s * (pairsum(a0) + pairsum(a1)));
        }
        issue(it + 3);
    }
}

// ---------------- epilogue ----------------
__global__ void k_combine(const float* __restrict__ xin, const float* __restrict__ root,
                          const float* __restrict__ bias, float* __restrict__ msgio,
                          float* __restrict__ outp, int dout, int relu) {
    int idx = blockIdx.x * blockDim.x + threadIdx.x;
    if (idx >= NN * dout) return;
    int nd = idx / dout, o = idx - nd * dout;
    float s = bias[o] + msgio[idx];
    msgio[idx] = 0.0f;
    const float4* xr = (const float4*)(xin + (nd << 6));
    #pragma unroll
    for (int i = 0; i < 16; i++) {
        float4 v = xr[i];
        s = fmaf(v.x, root[(4 * i + 0) * dout + o], s);
        s = fmaf(v.y, root[(4 * i + 1) * dout + o], s);
        s = fmaf(v.z, root[(4 * i + 2) * dout + o], s);
        s = fmaf(v.w, root[(4 * i + 3) * dout + o], s);
    }
    outp[idx] = relu ? fmaxf(s, 0.0f) : s;
}

__global__ void k_lsm(const float* __restrict__ acc, float* __restrict__ outp) {
    int n = blockIdx.x * blockDim.x + threadIdx.x;
    if (n >= NN) return;
    float v[8];
    #pragma unroll
    for (int c = 0; c < 8; c++) v[c] = acc[n * 8 + c];
    float m = v[0];
    #pragma unroll
    for (int c = 1; c < 8; c++) m = fmaxf(m, v[c]);
    float ssum = 0.0f;
    #pragma unroll
    for (int c = 0; c < 8; c++) ssum += expf(v[c] - m);
    float l = m + logf(ssum);
    #pragma unroll
    for (int c = 0; c < 8; c++) outp[n * 8 + c] = v[c] - l;
}

// ---------------- launch ----------------
extern "C" void kernel_launch(void* const* d_in, const int* in_sizes, int n_in,
                              void* d_out, int out_size) {
    const float* x      = (const float*)d_in[0];
    const int*   ei     = (const int*)d_in[1];
    const int*   et     = (const int*)d_in[2];
    const float* bases0 = (const float*)d_in[3];
    const float* comp0  = (const float*)d_in[4];
    const float* root0  = (const float*)d_in[5];
    const float* bias0  = (const float*)d_in[6];
    const float* bases1 = (const float*)d_in[7];
    const float* comp1  = (const float*)d_in[8];
    const float* root1  = (const float*)d_in[9];
    const float* bias1  = (const float*)d_in[10];
    const float* bases2 = (const float*)d_in[11];
    const float* comp2  = (const float*)d_in[12];
    const float* root2  = (const float*)d_in[13];
    const float* bias2  = (const float*)d_in[14];
    float* out = (float*)d_out;

    float *pH = nullptr, *pMsg = nullptr, *pAcc = nullptr, *pW0, *pW1;
    cudaGetSymbolAddress((void**)&pH, g_h);
    cudaGetSymbolAddress((void**)&pMsg, g_msg);
    cudaGetSymbolAddress((void**)&pAcc, g_acc);
    cudaGetSymbolAddress((void**)&pW0, g_W0);
    cudaGetSymbolAddress((void**)&pW1, g_W1);

    const int GX = 24;   // edge64: groups per relation = GX*4
    const int GX8 = 8;   // edge8: warps per relation = GX8*8

    // setup: 3 launches so the first k_edge64 is launch index 3 (ncu window)
    k_zero<<<2048, 256>>>();
    k_histW<<<dim3(512, 4), 256>>>(ei, et, comp0, bases0, comp1, bases1, comp2, bases2);
    k_permmeta<<<(EE + PCHUNK - 1) / PCHUNK, 256>>>(ei, et);

    // layer 0
    k_edge64<<<dim3(GX, RR), 256>>>(x, pW0, pMsg, GX * 4);
    k_combine<<<(NN * 64 + 255) / 256, 256>>>(x, root0, bias0, pMsg, pH, 64, 1);

    // layer 1
    k_edge64<<<dim3(GX, RR), 256>>>(pH, pW1, pMsg, GX * 4);
    k_combine<<<(NN * 64 + 255) / 256, 256>>>(pH, root1, bias1, pMsg, pAcc, 64, 1);

    // layer 2 (64 -> 8) + log_softmax
    k_edge8<<<dim3(GX8, RR), 256>>>(pAcc, pMsg, GX8 * 8);
    k_combine<<<(NN * 8 + 255) / 256, 256>>>(pAcc, root2, bias2, pMsg, pH, 8, 0);
    k_lsm<<<(NN + 255) / 256, 256>>>(pH, out);
}